// round 13
// baseline (speedup 1.0000x reference)
#include <cuda_runtime.h>
#include <cuda_bf16.h>

// DeformableConvLayer: B=4, H=W=256, C=64, K=3x3, UNITS=1.
// FUSED producer-consumer single kernel:
//   blocks [0,2048)    : phase 1 — P_k[pix]=<input[pix,:],kern[k,:]> for a
//                        128-pixel slice (4-chunk cp.async pipeline), then
//                        release-increment g_done[batch].
//   blocks [2048,4096) : phase 2 — spin (acquire) until the whole batch's
//                        planes are written, then the proven R6 select-gather
//                        on a 128-pixel half-row.
// Overlap: P2 blocks execute while later-batch P1 blocks still stream.

namespace {

constexpr int Hc = 256;
constexpr int Wc = 256;
constexpr int PIX = 4 * Hc * Wc;        // 262144
constexpr int NP1 = 2048;               // 128 px per P1 block; 512 per batch
constexpr int NP2 = 2048;               // 128 px per P2 block
constexpr int TB  = 128;

__device__ float g_P[9 * PIX];          // 9.4 MB tap-plane scratch
__device__ int   g_done[4];             // per-batch P1 completion counters

__device__ __forceinline__ unsigned long long fma2(unsigned long long a,
                                                   unsigned long long b,
                                                   unsigned long long c)
{
    unsigned long long d;
    asm("fma.rn.f32x2 %0, %1, %2, %3;" : "=l"(d) : "l"(a), "l"(b), "l"(c));
    return d;
}

struct P1Smem {
    float4 in_s[2][TB * 4];   // 2 x 8 KB ping-pong, [pixel][j ^ (pixel&3)]
    float4 w_s[9 * 16];       // 2.3 KB
};
struct P2Smem {
    float soff[TB * 18];      // 9.2 KB offsets for this half-row
    float smask[3 * 136];     // base-mask rows h-2..h, cols w0-2..w0+133
    float sP[9 * 136];        // base-tap P rows: plane k, row h+ky-2
};
constexpr unsigned SMEM_BYTES =
    sizeof(P1Smem) > sizeof(P2Smem) ? sizeof(P1Smem) : sizeof(P2Smem);

__global__ void dcn_zero()
{
    if (threadIdx.x < 4) g_done[threadIdx.x] = 0;
}

__device__ __forceinline__ void p1_issue_chunk(const float4* in4, P1Smem* s,
                                               int q, int t)
{
#pragma unroll
    for (int i = 0; i < 4; i++) {
        const int g = i * TB + t;            // 0..511
        const int p = g >> 2;                // pixel 0..127
        const int j = g & 3;
        const float4* src = &in4[(size_t)p * 16 + q * 4 + j];
        float4* dst = &s->in_s[q & 1][p * 4 + (j ^ (p & 3))];
        const unsigned sdst = (unsigned)__cvta_generic_to_shared(dst);
        asm volatile("cp.async.cg.shared.global [%0], [%1], 16;\n"
                     :: "r"(sdst), "l"(src));
    }
    asm volatile("cp.async.commit_group;\n");
}

__global__ __launch_bounds__(TB)
void dcn_fused(const float* __restrict__ input,    // [PIX,64]
               const float* __restrict__ mask,     // [256,256]
               const float* __restrict__ offset,   // [PIX,18]
               const float* __restrict__ kern,     // [9,64]
               const float* __restrict__ bias,
               float* __restrict__ out)            // [PIX]
{
    __shared__ __align__(16) unsigned char sraw[SMEM_BYTES];
    const int t = threadIdx.x;

    if (blockIdx.x < NP1) {
        // ================= PHASE 1 =================
        P1Smem* s = reinterpret_cast<P1Smem*>(sraw);
        const int pixbase = blockIdx.x * TB;

        for (int i = t; i < 9 * 16; i += TB)
            s->w_s[i] = reinterpret_cast<const float4*>(kern)[i];

        const float4* in4 = reinterpret_cast<const float4*>(input)
                            + (size_t)pixbase * 16;

        p1_issue_chunk(in4, s, 0, t);
        p1_issue_chunk(in4, s, 1, t);

        unsigned long long acc2[9];
#pragma unroll
        for (int k = 0; k < 9; k++) acc2[k] = 0ull;

#pragma unroll
        for (int q = 0; q < 4; q++) {
            if (q < 3)
                asm volatile("cp.async.wait_group 1;\n" ::: "memory");
            else
                asm volatile("cp.async.wait_group 0;\n" ::: "memory");
            __syncthreads();

#pragma unroll
            for (int j = 0; j < 4; j++) {
                const ulonglong2 v = *reinterpret_cast<const ulonglong2*>(
                                         &s->in_s[q & 1][t * 4 + (j ^ (t & 3))]);
#pragma unroll
                for (int k = 0; k < 9; k++) {
                    const ulonglong2 wv = *reinterpret_cast<const ulonglong2*>(
                                              &s->w_s[k * 16 + q * 4 + j]);
                    acc2[k] = fma2(v.x, wv.x, acc2[k]);
                    acc2[k] = fma2(v.y, wv.y, acc2[k]);
                }
            }
            if (q < 2) {
                __syncthreads();
                p1_issue_chunk(in4, s, q + 2, t);
            }
        }

#pragma unroll
        for (int k = 0; k < 9; k++) {
            float lo, hi;
            asm("mov.b64 {%0, %1}, %2;" : "=f"(lo), "=f"(hi) : "l"(acc2[k]));
            g_P[k * PIX + pixbase + t] = lo + hi;
        }

        // signal: this 128-pixel slice of the batch's planes is globally visible
        __threadfence();
        __syncthreads();
        if (t == 0) {
            const int batch = blockIdx.x >> 9;      // 512 P1 blocks per batch
            asm volatile("red.release.gpu.global.add.s32 [%0], 1;"
                         :: "l"(&g_done[batch]) : "memory");
        }
    } else {
        // ================= PHASE 2 =================
        P2Smem* s = reinterpret_cast<P2Smem*>(sraw);
        const int j    = blockIdx.x - NP1;
        const int pix0 = j * TB;
        const int b  = pix0 >> 16;
        const int h  = (pix0 >> 8) & 255;
        const int w0 = pix0 & 255;               // 0 or 128
        const int w  = w0 + t;
        const float* Pb = g_P + (size_t)b * (Hc * Wc);

        // wait until all 512 P1 blocks of this batch have released
        if (t == 0) {
            int v;
            do {
                asm volatile("ld.acquire.gpu.global.b32 %0, [%1];"
                             : "=r"(v) : "l"(&g_done[b]) : "memory");
                if (v < 512) __nanosleep(128);
            } while (v < 512);
        }
        __syncthreads();

        // stage offsets: 576 float4, coalesced
        {
            const float4* off4 = reinterpret_cast<const float4*>(
                                     offset + (size_t)pix0 * 18);
            float4* soff4 = reinterpret_cast<float4*>(s->soff);
#pragma unroll
            for (int i = 0; i < 4; i++)
                soff4[i * TB + t] = off4[i * TB + t];
            if (t < 576 - 4 * TB)
                soff4[4 * TB + t] = off4[4 * TB + t];
        }
        // stage base-mask rows h-2..h, cols w0-2..w0+133
        for (int i = t; i < 3 * 136; i += TB) {
            const int r = i / 136, c = i - r * 136;
            const int row = h - 2 + r, col = w0 - 2 + c;
            s->smask[i] = (row >= 0 && col >= 0 && col <= 255)
                              ? mask[row * Wc + col] : 0.0f;
        }
        // stage base-tap P rows (after spin: planes final)
        for (int i = t; i < 9 * 136; i += TB) {
            const int k = i / 136, c = i - k * 136;
            const int row = h + k / 3 - 2, col = w0 - 2 + c;
            s->sP[i] = (row >= 0 && col >= 0 && col <= 255)
                           ? g_P[k * PIX + b * (Hc * Wc) + row * Wc + col] : 0.0f;
        }
        __syncthreads();

        // single wave: 9 offset-path P gathers + 9 offset-mask gathers
        float Vo[9], pmoff[9];
#pragma unroll
        for (int k = 0; k < 9; k++) {
            const int ky = k / 3;
            const int kx = k - ky * 3;
            const int yb = h + ky - 1;
            const int xb = w + kx - 1;
            const bool inb = (yb >= 0) & (yb < Hc) & (xb >= 0) & (xb < Wc);
            const int yi = inb ? yb : 0;
            const int xi = inb ? xb : 0;

            const float2 off2 = *reinterpret_cast<const float2*>(
                                    &s->soff[t * 18 + 2 * k]);

            const float yf = fminf(fmaxf((float)yi + off2.x, 0.0f), 255.0f);
            const float xf = fminf(fmaxf((float)xi + off2.y, 0.0f), 255.0f);
            const int y0 = (int)floorf(yf);
            const int x0 = (int)floorf(xf);
            Vo[k] = ((y0 >= 1) & (x0 >= 1))
                        ? Pb[k * PIX + (y0 - 1) * Wc + (x0 - 1)] : 0.0f;

            int yo = (int)floorf((float)yi + off2.x);
            int xo = (int)floorf((float)xi + off2.y);
            yo = min(max(yo, 0), Hc + 1);
            xo = min(max(xo, 0), Wc + 1);
            pmoff[k] = ((yo >= 1) & (yo <= Hc) & (xo >= 1) & (xo <= Wc))
                           ? mask[(yo - 1) * Wc + (xo - 1)] : 0.0f;
        }

        float acc = __ldg(bias);
#pragma unroll
        for (int k = 0; k < 9; k++) {
            const int ky = k / 3;
            const int kx = k - ky * 3;
            const int yb = h + ky - 1;
            const int xb = w + kx - 1;
            const bool base_ok = (yb >= 1) & (yb < Hc) & (xb >= 1) & (xb < Wc);
            const float pmask = base_ok ? s->smask[ky * 136 + (t + kx)] : 0.0f;
            const float Vb    = base_ok ? s->sP[k * 136 + (t + kx)] : 0.0f;
            acc += (pmask != pmoff[k]) ? Vo[k] : Vb;
        }

        out[pix0 + t] = acc;
    }
}

} // namespace

extern "C" void kernel_launch(void* const* d_in, const int* in_sizes, int n_in,
                              void* d_out, int out_size)
{
    const float* input  = (const float*)d_in[0];   // [4,256,256,64]
    const float* mask   = (const float*)d_in[1];   // [1,256,256,1]
    const float* offset = (const float*)d_in[2];   // [4,256,256,18]
    const float* kern   = (const float*)d_in[3];   // [3,3,64,1]
    const float* bias   = (const float*)d_in[4];   // [1]
    float* out = (float*)d_out;

    dcn_zero<<<1, 32>>>();
    dcn_fused<<<NP1 + NP2, TB>>>(input, mask, offset, kern, bias, out);
}

// round 14
// speedup vs baseline: 1.4100x; 1.4100x over previous
#include <cuda_runtime.h>
#include <cuda_bf16.h>

// DeformableConvLayer: B=4, H=W=256, C=64, K=3x3, UNITS=1.
// Two kernels (exact R9 bodies) overlapped via Programmatic Dependent Launch:
//   P1 issues griddepcontrol.launch_dependents at CTA entry -> P2 blocks launch
//   while P1's last wave drains. P2 stages offset/mask rows immediately, then
//   acquire-spins on a per-batch counter (released by P1 after plane stores).
//   Counters are self-cleaning (last P2 block per batch resets them) so the
//   sequence is graph-replay deterministic with no zeroing kernel.

namespace {

constexpr int Hc = 256;
constexpr int Wc = 256;
constexpr int PIX = 4 * Hc * Wc;               // 262144

__device__ float g_P[9 * PIX];                 // 9.4 MB tap-plane scratch
__device__ int   g_done[4];                    // P1 blocks completed per batch (512 target)
__device__ int   g_p2done[4];                  // P2 blocks completed per batch (256 target)

__device__ __forceinline__ unsigned long long fma2(unsigned long long a,
                                                   unsigned long long b,
                                                   unsigned long long c)
{
    unsigned long long d;
    asm("fma.rn.f32x2 %0, %1, %2, %3;" : "=l"(d) : "l"(a), "l"(b), "l"(c));
    return d;
}

// ---------------- Phase 1: double-buffered contraction (R9) ----------------
constexpr int P1_T = 128;

__global__ __launch_bounds__(P1_T)
void dcn_phase1(const float* __restrict__ input,   // [PIX, 64]
                const float* __restrict__ kern)    // [9, 64]
{
    // Allow dependent (phase 2) grid to start launching as soon as every P1
    // CTA has begun. Scheduling-only; data readiness is the g_done protocol.
    asm volatile("griddepcontrol.launch_dependents;" ::: "memory");

    __shared__ float4 in_s[2][P1_T * 8];  // 2 x 16 KB, [pixel][c4 ^ (pixel&7)]
    __shared__ float4 w_s[9 * 16];        // 2.3 KB

    const int t = threadIdx.x;
    const int pixbase = blockIdx.x * P1_T;

    for (int i = t; i < 9 * 16; i += P1_T)
        w_s[i] = reinterpret_cast<const float4*>(kern)[i];

    const float4* in4 = reinterpret_cast<const float4*>(input) + (size_t)pixbase * 16;

#pragma unroll
    for (int half = 0; half < 2; half++) {
#pragma unroll
        for (int i = 0; i < 8; i++) {
            const int g  = i * P1_T + t;
            const int p  = g >> 3;
            const int c4 = g & 7;
            const float4* src = &in4[(size_t)p * 16 + half * 8 + c4];
            float4* dst = &in_s[half][p * 8 + (c4 ^ (p & 7))];
            const unsigned sdst = (unsigned)__cvta_generic_to_shared(dst);
            asm volatile("cp.async.cg.shared.global [%0], [%1], 16;\n"
                         :: "r"(sdst), "l"(src));
        }
        asm volatile("cp.async.commit_group;\n");
    }

    unsigned long long acc2[9];
#pragma unroll
    for (int k = 0; k < 9; k++) acc2[k] = 0ull;

    asm volatile("cp.async.wait_group 1;\n" ::: "memory");
    __syncthreads();
#pragma unroll
    for (int c4 = 0; c4 < 8; c4++) {
        const ulonglong2 v = *reinterpret_cast<const ulonglong2*>(
                                 &in_s[0][t * 8 + (c4 ^ (t & 7))]);
#pragma unroll
        for (int k = 0; k < 9; k++) {
            const ulonglong2 wv = *reinterpret_cast<const ulonglong2*>(&w_s[k * 16 + c4]);
            acc2[k] = fma2(v.x, wv.x, acc2[k]);
            acc2[k] = fma2(v.y, wv.y, acc2[k]);
        }
    }

    asm volatile("cp.async.wait_group 0;\n" ::: "memory");
    __syncthreads();
#pragma unroll
    for (int c4 = 0; c4 < 8; c4++) {
        const ulonglong2 v = *reinterpret_cast<const ulonglong2*>(
                                 &in_s[1][t * 8 + (c4 ^ (t & 7))]);
#pragma unroll
        for (int k = 0; k < 9; k++) {
            const ulonglong2 wv = *reinterpret_cast<const ulonglong2*>(&w_s[k * 16 + 8 + c4]);
            acc2[k] = fma2(v.x, wv.x, acc2[k]);
            acc2[k] = fma2(v.y, wv.y, acc2[k]);
        }
    }

#pragma unroll
    for (int k = 0; k < 9; k++) {
        float lo, hi;
        asm("mov.b64 {%0, %1}, %2;" : "=f"(lo), "=f"(hi) : "l"(acc2[k]));
        g_P[k * PIX + pixbase + t] = lo + hi;
    }

    // release this block's contribution: planes slice globally visible
    __threadfence();
    __syncthreads();
    if (t == 0) {
        const int batch = blockIdx.x >> 9;        // 512 P1 blocks per batch
        asm volatile("red.release.gpu.global.add.s32 [%0], 1;"
                     :: "l"(&g_done[batch]) : "memory");
    }
}

// ---------------- Phase 2: one-wave select-gather (R9) + acquire-spin ----------------
constexpr int P2_T = 256;

__global__ __launch_bounds__(P2_T)
void dcn_phase2(const float* __restrict__ mask,     // [256,256]
                const float* __restrict__ offset,   // [PIX,18]
                const float* __restrict__ bias,
                float* __restrict__ out)            // [PIX]
{
    __shared__ float soff[P2_T * 18];    // 18 KB offsets for this row
    __shared__ float smask[3 * 256];     // base-mask rows h-2..h
    __shared__ float sP[9 * 256];        // base-tap P rows: plane k, row h+ky-2

    const int t = threadIdx.x;
    const int pixbase = blockIdx.x * P2_T;   // one image row per block
    const int b = pixbase >> 16;
    const int h = (pixbase >> 8) & 255;
    const int w = t;
    const float* Pb = g_P + (size_t)b * (Hc * Wc);

    // ---- stage inputs that do NOT depend on phase 1 (overlaps P1 tail) ----
    {   // offsets: 1152 float4, coalesced
        const float4* off4 = reinterpret_cast<const float4*>(offset + (size_t)pixbase * 18);
        float4* soff4 = reinterpret_cast<float4*>(soff);
#pragma unroll
        for (int i = 0; i < 4; i++)
            soff4[i * P2_T + t] = off4[i * P2_T + t];
        if (t < 1152 - 4 * P2_T)
            soff4[4 * P2_T + t] = off4[4 * P2_T + t];
    }
#pragma unroll
    for (int r = 0; r < 3; r++) {
        const int row = h - 2 + r;
        smask[r * 256 + t] = (row >= 0) ? mask[row * Wc + t] : 0.0f;
    }

    // ---- wait for this batch's planes ----
    if (t == 0) {
        int v;
        do {
            asm volatile("ld.acquire.gpu.global.b32 %0, [%1];"
                         : "=r"(v) : "l"(&g_done[b]) : "memory");
            if (v < 512) __nanosleep(64);
        } while (v < 512);
    }
    __syncthreads();

#pragma unroll
    for (int k = 0; k < 9; k++) {        // base-tap P rows (coalesced)
        const int row = h + k / 3 - 2;
        sP[k * 256 + t] = (row >= 0) ? g_P[k * PIX + b * (Hc * Wc) + row * Wc + t]
                                     : 0.0f;
    }
    __syncthreads();

    // ---- single wave: 9 offset-path P gathers + 9 offset-mask gathers ----
    float Vo[9], pmoff[9];
#pragma unroll
    for (int k = 0; k < 9; k++) {
        const int ky = k / 3;
        const int kx = k - ky * 3;
        const int yb = h + ky - 1;
        const int xb = w + kx - 1;
        const bool inb = (yb >= 0) & (yb < Hc) & (xb >= 0) & (xb < Wc);
        const int yi = inb ? yb : 0;
        const int xi = inb ? xb : 0;

        const float2 off2 = *reinterpret_cast<const float2*>(&soff[t * 18 + 2 * k]);

        // offset-path final coords (diff==1 case): clip(yi+off, 0, 255), floor
        const float yf = fminf(fmaxf((float)yi + off2.x, 0.0f), 255.0f);
        const float xf = fminf(fmaxf((float)xi + off2.y, 0.0f), 255.0f);
        const int y0 = (int)floorf(yf);
        const int x0 = (int)floorf(xf);
        Vo[k] = ((y0 >= 1) & (x0 >= 1))
                    ? Pb[k * PIX + (y0 - 1) * Wc + (x0 - 1)] : 0.0f;

        // mask at offset point (padded coords, floor + clip to [0,257])
        int yo = (int)floorf((float)yi + off2.x);
        int xo = (int)floorf((float)xi + off2.y);
        yo = min(max(yo, 0), Hc + 1);
        xo = min(max(xo, 0), Wc + 1);
        pmoff[k] = ((yo >= 1) & (yo <= Hc) & (xo >= 1) & (xo <= Wc))
                       ? mask[(yo - 1) * Wc + (xo - 1)] : 0.0f;
    }

    // ---- select + sum (smem-only consumers) ----
    float acc = __ldg(bias);
#pragma unroll
    for (int k = 0; k < 9; k++) {
        const int ky = k / 3;
        const int kx = k - ky * 3;
        const int yb = h + ky - 1;
        const int xb = w + kx - 1;
        const bool base_ok = (yb >= 1) & (yb < Hc) & (xb >= 1) & (xb < Wc);
        const float pmask = base_ok ? smask[ky * 256 + (w + kx - 2)] : 0.0f;
        const float Vb    = base_ok ? sP[k * 256 + (w + kx - 2)] : 0.0f;
        acc += (pmask != pmoff[k]) ? Vo[k] : Vb;
    }

    out[pixbase + t] = acc;

    // ---- self-cleaning counters: last P2 block of this batch resets both ----
    __syncthreads();
    if (t == 0) {
        const int old = atomicAdd(&g_p2done[b], 1);
        if (old == 255) {                 // 256 P2 blocks per batch
            atomicExch(&g_done[b], 0);
            atomicExch(&g_p2done[b], 0);
        }
    }
}

} // namespace

extern "C" void kernel_launch(void* const* d_in, const int* in_sizes, int n_in,
                              void* d_out, int out_size)
{
    const float* input  = (const float*)d_in[0];   // [4,256,256,64]
    const float* mask   = (const float*)d_in[1];   // [1,256,256,1]
    const float* offset = (const float*)d_in[2];   // [4,256,256,18]
    const float* kern   = (const float*)d_in[3];   // [3,3,64,1]
    const float* bias   = (const float*)d_in[4];   // [1]
    float* out = (float*)d_out;

    dcn_phase1<<<PIX / P1_T, P1_T>>>(input, kern);

    // Phase 2 with Programmatic Dependent Launch: may begin while phase 1 drains.
    cudaLaunchConfig_t cfg = {};
    cfg.gridDim  = dim3(PIX / P2_T);
    cfg.blockDim = dim3(P2_T);
    cfg.dynamicSmemBytes = 0;
    cfg.stream = 0;
    cudaLaunchAttribute attrs[1];
    attrs[0].id = cudaLaunchAttributeProgrammaticStreamSerialization;
    attrs[0].val.programmaticStreamSerializationAllowed = 1;
    cfg.attrs = attrs;
    cfg.numAttrs = 1;
    cudaLaunchKernelEx(&cfg, dcn_phase2, mask, offset, bias, (float*)out);
}